// round 17
// baseline (speedup 1.0000x reference)
#include <cuda_runtime.h>

// YOLOv2 loss, B=64, A=5, C=80, G=32, N=50. Merged single block type, FINE
// granularity: 1280 blocks x 256 thr x 1 box/thread; 2-3 gather GTs per block.
#define NGT 50
#define NBLOCKS 1280             // 64 batches x 20 segs of 256 boxes

__device__ float g_noobj[NBLOCKS];
__device__ float g_prior[NBLOCKS];
__device__ float g_coord[NBLOCKS];
__device__ float g_obj[NBLOCKS];
__device__ float g_cls[NBLOCKS];
__device__ unsigned int g_count = 0;

__device__ __forceinline__ float sigm(float x) {
    float t;
    asm("tanh.approx.f32 %0, %1;" : "=f"(t) : "f"(0.5f * x));
    return fmaf(0.5f, t, 0.5f);
}

__global__ void __launch_bounds__(256, 8) fused_kernel(const float* __restrict__ pred,
                                                       const float* __restrict__ gt,
                                                       const float* __restrict__ anc,
                                                       const int* __restrict__ seen,
                                                       float* __restrict__ out)
{
    int tid = threadIdx.x;
    int wid = tid >> 5, lane = tid & 31;

    __shared__ float4 sbox[NGT];       // gt xyxy by GT index
    __shared__ float4 cbox[NGT + 5];   // compacted + padded gt xyxy
    __shared__ float  cssa[NGT + 5];   // compacted + padded 0.375*gt_area
    __shared__ float  swmax[8];        // per-warp max of sb
    __shared__ unsigned int sbal[2];
    __shared__ unsigned char flag[256];
    __shared__ float  sred[16];
    __shared__ float  gc[3], go[3], gl[3];   // gather results (up to 3 warps)

    int b    = blockIdx.x / 20;
    int seg  = blockIdx.x % 20;
    int base = seg * 256;
    int a    = base >> 10;             // uniform anchor for this block
    int cb   = base & 1023;
    int c    = cb + tid;               // one box per thread, coalesced loads
    const float* pp = pred + (((size_t)(b * 425 + a * 85)) << 10);

    // main-path loads issued first
    float dx = pp[c], dy = pp[c + 1024], tw = pp[c + 2048], th = pp[c + 3072], to = pp[c + 4096];

    flag[tid] = 0;

    int mybb = -1; float ga_r = 0.0f;
    if (tid < NGT) {
        const float* g = gt + (size_t)(b * NGT + tid) * 7;
        float gdx = g[0], gdy = g[1], gx = g[2], gy = g[3], gw = g[4], gh = g[5];
        ga_r = gw * gh;
        float best = -1.0f; int bp = 0;
        #pragma unroll
        for (int aa = 0; aa < 5; aa++) {
            float aw = __ldg(&anc[2 * aa]), ah = __ldg(&anc[2 * aa + 1]);
            float it = fminf(gw, aw) * fminf(gh, ah);
            float iou = __fdividef(it, ga_r + aw * ah - it);
            if (iou > best) { best = iou; bp = aa; }
        }
        mybb = bp * 1024 + (int)gy * 32 + (int)gx;
        float cx = gdx + gx * (1.0f / 32.0f), cy = gdy + gy * (1.0f / 32.0f);
        sbox[tid] = make_float4(cx - 0.5f * gw, cy - 0.5f * gh, cx + 0.5f * gw, cy + 0.5f * gh);
    }

    // ===== GATHER SECTION: 3 GTs for segs 0-9, 2 GTs for segs 10-19 =====
    int ngath = (seg < 10) ? 3 : 2;
    if (wid < ngath) {
        int gtid = b * NGT + ((seg < 10) ? seg * 3 : 30 + (seg - 10) * 2) + wid;
        const float* g = gt + (size_t)gtid * 7;      // broadcast loads
        float gdx = g[0], gdy = g[1], gx = g[2], gy = g[3], gw = g[4], gh = g[5];
        int k = (int)g[6];
        float ga = gw * gh;
        float best = -1.0f; int bp = 0;
        #pragma unroll
        for (int aa = 0; aa < 5; aa++) {
            float aw = __ldg(&anc[2 * aa]), ah = __ldg(&anc[2 * aa + 1]);
            float it = fminf(gw, aw) * fminf(gh, ah);
            float iou = __fdividef(it, ga + aw * ah - it);
            if (iou > best) { best = iou; bp = aa; }
        }
        int cell = (int)gy * 32 + (int)gx;
        const float* gp = pred + (((size_t)(b * 425 + bp * 85)) << 10) + cell;

        float S = 0.0f, Q = 0.0f, ek = 0.0f;
        {
            float e0 = __expf(gp[(size_t)(5 + lane) << 10]);  S += e0; Q += e0 * e0; if (lane == k) ek = e0;
            float e1 = __expf(gp[(size_t)(37 + lane) << 10]); S += e1; Q += e1 * e1; if (lane + 32 == k) ek = e1;
            if (lane < 16) {
                float e2 = __expf(gp[(size_t)(69 + lane) << 10]); S += e2; Q += e2 * e2; if (lane + 64 == k) ek = e2;
            }
        }
        #pragma unroll
        for (int off = 16; off; off >>= 1) {
            S  += __shfl_xor_sync(0xffffffffu, S,  off);
            Q  += __shfl_xor_sync(0xffffffffu, Q,  off);
            ek += __shfl_xor_sync(0xffffffffu, ek, off);
        }

        float sdxg = sigm(gp[0]), sdyg = sigm(gp[1024]);
        float twg = gp[2048], thg = gp[3072], sobj = sigm(gp[4096]);
        float aw = __ldg(&anc[2 * bp]), ah = __ldg(&anc[2 * bp + 1]);
        float d0 = sdxg - gdx, d1 = sdyg - gdy;
        float d2 = twg - (__logf(gw) - __logf(aw));
        float d3 = thg - (__logf(gh) - __logf(ah));

        float cxg = sdxg + (float)(cell & 31) * (1.0f / 32.0f);
        float cyg = sdyg + (float)(cell >> 5) * (1.0f / 32.0f);
        float pwg = aw * __expf(twg), phg = ah * __expf(thg);
        float gxx = (gdx + gx * (1.0f / 32.0f)) - 0.5f * gw;
        float gyy = (gdy + gy * (1.0f / 32.0f)) - 0.5f * gh;
        float w = fminf(cxg + 0.5f * pwg, gxx + gw) - fmaxf(cxg - 0.5f * pwg, gxx);
        float h = fminf(cyg + 0.5f * phg, gyy + gh) - fmaxf(cyg - 0.5f * phg, gyy);
        float inter = fmaxf(w, 0.0f) * fmaxf(h, 0.0f);
        float iou_t = __fdividef(inter, ga + pwg * phg - inter);
        float di = sobj - iou_t;
        float invS = __fdividef(1.0f, S);
        if (lane == 0) {
            gc[wid] = d0*d0 + d1*d1 + d2*d2 + d3*d3;
            go[wid] = di * di;
            gl[wid] = fmaf(Q * invS, invS, fmaf(-2.0f * ek, invS, 1.0f));
        }
    }

    // ===== MAIN SECTION: one box per thread =====
    float sdx = sigm(dx), sdy = sigm(dy), so = sigm(to);
    float cx = sdx + (float)(c & 31) * (1.0f / 32.0f);
    float cy = sdy + (float)(c >> 5) * (1.0f / 32.0f);
    float aw = __ldg(&anc[2 * a]), ah = __ldg(&anc[2 * a + 1]);
    float pw = aw * __expf(tw), ph = ah * __expf(th);
    float x1 = cx - 0.5f * pw, y1 = cy - 0.5f * ph;
    float x2 = cx + 0.5f * pw, y2 = cy + 0.5f * ph;
    float sb = pw * ph, t_ = 0.375f * sb;

    float sbm = sb;
    #pragma unroll
    for (int off = 16; off; off >>= 1)
        sbm = fmaxf(sbm, __shfl_xor_sync(0xffffffffu, sbm, off));
    if (lane == 0) swmax[wid] = sbm;
    __syncthreads();   // sbox, swmax, gc/go/gl, zeroed flags visible

    if (mybb >= base && mybb < base + 256) flag[mybb - base] = 1;

    // exact prune: GT n can trigger only if 0.6*ga_n < max_block(sb)  (inter <= sb)
    float bmax = fmaxf(fmaxf(fmaxf(swmax[0], swmax[1]), fmaxf(swmax[2], swmax[3])),
                       fmaxf(fmaxf(swmax[4], swmax[5]), fmaxf(swmax[6], swmax[7])));
    bool keep = (tid < NGT) && (0.6f * ga_r < bmax);
    if (wid < 2) {
        unsigned int bal = __ballot_sync(0xffffffffu, keep);
        if (lane == 0) sbal[wid] = bal;
    }
    __syncthreads();   // flags + ballots visible
    unsigned int bal0 = sbal[0], bal1 = sbal[1];
    int cnt0 = __popc(bal0);
    int cnt  = cnt0 + __popc(bal1);
    int padded = (cnt + 4) / 5 * 5;
    if (keep) {
        unsigned int mybal = (wid == 0) ? bal0 : bal1;
        int pos = (wid == 0 ? 0 : cnt0) + __popc(mybal & ((1u << lane) - 1u));
        cbox[pos] = sbox[tid];
        cssa[pos] = 0.375f * ga_r;
    }
    if (tid < padded - cnt) {
        cbox[cnt + tid] = make_float4(1e30f, 1e30f, -1e30f, -1e30f);
        cssa[cnt + tid] = 1e30f;
    }
    __syncthreads();   // compacted list ready

    bool ib = flag[tid] != 0;
    float noc = (!ib) ? so * so : 0.0f;
    float pr = 0.0f;
    if (!ib) {
        float d0 = sdx - 0.015625f, d1 = sdy - 0.015625f;
        pr = d0*d0 + d1*d1 + tw*tw + th*th;
    }

    // over-test:  iou > 0.6  <=>  inter - 0.375*sa > 0.375*sb   (division-free)
    float m = -1e30f;
    for (int n = 0; n < padded; n += 5) {
        #pragma unroll
        for (int u = 0; u < 5; u++) {
            float4 gb = cbox[n + u]; float s6 = cssa[n + u];
            float w = fminf(x2, gb.z) - fmaxf(x1, gb.x);
            float h = fminf(y2, gb.w) - fmaxf(y1, gb.y);
            m = fmaxf(m, fmaf(fmaxf(w, 0.0f), h, -s6));
        }
    }
    float no = (m > t_) ? 0.0f : noc;

    #pragma unroll
    for (int off = 16; off; off >>= 1) {
        no += __shfl_down_sync(0xffffffffu, no, off);
        pr += __shfl_down_sync(0xffffffffu, pr, off);
    }
    if (lane == 0) { sred[wid] = no; sred[8 + wid] = pr; }
    __syncthreads();
    if (tid == 0) {
        float s = 0.0f;
        #pragma unroll
        for (int i = 0; i < 8; i++) s += sred[i];
        g_noobj[blockIdx.x] = s;
    }
    if (tid == 32) {
        float s = 0.0f;
        #pragma unroll
        for (int i = 0; i < 8; i++) s += sred[8 + i];
        g_prior[blockIdx.x] = s;
    }
    if (tid == 64) {
        float tc = 0.f, to_ = 0.f, tl = 0.f;
        for (int i = 0; i < ngath; i++) { tc += gc[i]; to_ += go[i]; tl += gl[i]; }
        g_coord[blockIdx.x] = tc;
        g_obj[blockIdx.x]   = to_;
        g_cls[blockIdx.x]   = tl;
    }

    // ---------------- last-block deterministic final combine ----------------
    __shared__ bool is_last;
    __shared__ float sm[40];
    __syncthreads();
    if (threadIdx.x == 0) {
        __threadfence();
        unsigned int cnt_ = atomicAdd(&g_count, 1u);
        is_last = (cnt_ == NBLOCKS - 1);
    }
    __syncthreads();
    if (!is_last) return;
    __threadfence();  // make all blocks' partials visible

    float a0 = 0.f, a1 = 0.f, a2 = 0.f, a3 = 0.f, a4 = 0.f;
    for (int i = tid; i < NBLOCKS; i += 256) {
        a0 += g_noobj[i]; a1 += g_prior[i];
        a2 += g_coord[i]; a3 += g_obj[i]; a4 += g_cls[i];
    }
    #pragma unroll
    for (int off = 16; off; off >>= 1) {
        a0 += __shfl_down_sync(0xffffffffu, a0, off);
        a1 += __shfl_down_sync(0xffffffffu, a1, off);
        a2 += __shfl_down_sync(0xffffffffu, a2, off);
        a3 += __shfl_down_sync(0xffffffffu, a3, off);
        a4 += __shfl_down_sync(0xffffffffu, a4, off);
    }
    if (lane == 0) {
        sm[wid] = a0; sm[8 + wid] = a1; sm[16 + wid] = a2; sm[24 + wid] = a3; sm[32 + wid] = a4;
    }
    __syncthreads();
    if (tid == 0) {
        float t0 = 0.f, t1 = 0.f, t2 = 0.f, t3 = 0.f, t4 = 0.f;
        #pragma unroll
        for (int i = 0; i < 8; i++) {
            t0 += sm[i]; t1 += sm[8 + i]; t2 += sm[16 + i]; t3 += sm[24 + i]; t4 += sm[32 + i];
        }
        float lp = (seen[0] < 12800) ? 0.01f : 0.0f;
        out[0] = t4 + t0 + 5.0f * t3 + t2 + lp * t1;
        g_count = 0;   // reset for next graph replay
    }
}

extern "C" void kernel_launch(void* const* d_in, const int* in_sizes, int n_in,
                              void* d_out, int out_size) {
    const float* pred = (const float*)d_in[0];
    const float* gt   = (const float*)d_in[1];
    const float* anc  = (const float*)d_in[2];
    const int*   seen = (const int*)d_in[3];
    (void)in_sizes; (void)n_in; (void)out_size;

    fused_kernel<<<NBLOCKS, 256>>>(pred, gt, anc, seen, (float*)d_out);
}